// round 2
// baseline (speedup 1.0000x reference)
#include <cuda_runtime.h>
#include <math.h>

#define SN     16384
#define E_DIM  512
#define C_DIM  1024
#define G_NUM  32
#define CG_NUM 32

#define BM 128
#define BN 64
#define BK 32
#define TM 8

// scratch (static device globals: no allocation)
__device__ float g_W2T[C_DIM * E_DIM];          // 2 MB: W2 transposed to (C, E)
__device__ int   g_idx[SN * G_NUM];             // packed argmax indices per (row, group)
__device__ float g_coef[SN * G_NUM * 2];        // exact straight-through coefficients

// ---------- packed fp32x2 helpers (FFMA2 — PTX-only path) ----------
__device__ __forceinline__ unsigned long long pack2(float x, float y) {
    unsigned long long u;
    asm("mov.b64 %0, {%1, %2};" : "=l"(u) : "f"(x), "f"(y));
    return u;
}
__device__ __forceinline__ float2 unpack2(unsigned long long u) {
    float2 v;
    asm("mov.b64 {%0, %1}, %2;" : "=f"(v.x), "=f"(v.y) : "l"(u));
    return v;
}
__device__ __forceinline__ unsigned long long ffma2(unsigned long long a,
                                                    unsigned long long b,
                                                    unsigned long long c) {
    unsigned long long d;
    asm("fma.rn.f32x2 %0, %1, %2, %3;" : "=l"(d) : "l"(a), "l"(b), "l"(c));
    return d;
}

// ---------- K0: transpose W2 (E, C) -> g_W2T (C, E) ----------
__global__ void k_transpose(const float* __restrict__ W2) {
    __shared__ float tile[32][33];
    const int bx = blockIdx.x;   // c tile: C/32 = 32
    const int by = blockIdx.y;   // e tile: E/32 = 16
    const int tx = threadIdx.x;  // 0..31
    const int ty = threadIdx.y;  // 0..7
#pragma unroll
    for (int j = 0; j < 4; j++) {
        int e = by * 32 + ty + j * 8;
        int c = bx * 32 + tx;
        tile[ty + j * 8][tx] = W2[e * C_DIM + c];
    }
    __syncthreads();
#pragma unroll
    for (int j = 0; j < 4; j++) {
        int c = bx * 32 + ty + j * 8;
        int e = by * 32 + tx;
        g_W2T[c * E_DIM + e] = tile[tx][ty + j * 8];
    }
}

// ---------- K1: fp32 GEMM (logits) + group softmax + Gumbel argmax sampling ----------
__global__ __launch_bounds__(256, 2)
void k_gemm_sample(const float* __restrict__ x, const float* __restrict__ W1,
                   const float* __restrict__ b1, const float* __restrict__ coff,
                   const float* __restrict__ g1, const float* __restrict__ g2,
                   const float* __restrict__ wint, const float* __restrict__ uint_,
                   float* __restrict__ out_sampled, float* __restrict__ out_soft) {
    __shared__ float smem[BM * (BN + 1)];      // 33,280 B; unions GEMM tiles and logits
    float* As = smem;                          // [BK][BM+1] = 32*129
    float* Bs = smem + BK * (BM + 1);          // [BK][BN+1] = 32*65

    const int tid  = threadIdx.x;
    const int row0 = blockIdx.y * BM;
    const int col0 = blockIdx.x * BN;
    const int tx = tid & 15;
    const int ty = tid >> 4;
    const int rb = ty * TM;
    const int cb = tx * 4;

    unsigned long long acc[TM][2];
#pragma unroll
    for (int i = 0; i < TM; i++) { acc[i][0] = 0ull; acc[i][1] = 0ull; }

    for (int kk = 0; kk < E_DIM; kk += BK) {
#pragma unroll
        for (int p = 0; p < 4; p++) {
            int idx = p * 256 + tid;
            int r = idx >> 3, kq = idx & 7;
            float4 v = *reinterpret_cast<const float4*>(&x[(row0 + r) * E_DIM + kk + kq * 4]);
            As[(kq * 4 + 0) * (BM + 1) + r] = v.x;
            As[(kq * 4 + 1) * (BM + 1) + r] = v.y;
            As[(kq * 4 + 2) * (BM + 1) + r] = v.z;
            As[(kq * 4 + 3) * (BM + 1) + r] = v.w;
        }
#pragma unroll
        for (int p = 0; p < 2; p++) {
            int idx = p * 256 + tid;
            int r = idx >> 3, kq = idx & 7;
            float4 v = *reinterpret_cast<const float4*>(&W1[(col0 + r) * E_DIM + kk + kq * 4]);
            Bs[(kq * 4 + 0) * (BN + 1) + r] = v.x;
            Bs[(kq * 4 + 1) * (BN + 1) + r] = v.y;
            Bs[(kq * 4 + 2) * (BN + 1) + r] = v.z;
            Bs[(kq * 4 + 3) * (BN + 1) + r] = v.w;
        }
        __syncthreads();
#pragma unroll
        for (int k = 0; k < BK; k++) {
            unsigned long long b01 = pack2(Bs[k * (BN + 1) + cb + 0], Bs[k * (BN + 1) + cb + 1]);
            unsigned long long b23 = pack2(Bs[k * (BN + 1) + cb + 2], Bs[k * (BN + 1) + cb + 3]);
#pragma unroll
            for (int i = 0; i < TM; i++) {
                float a = As[k * (BM + 1) + rb + i];
                unsigned long long aa = pack2(a, a);
                acc[i][0] = ffma2(aa, b01, acc[i][0]);
                acc[i][1] = ffma2(aa, b23, acc[i][1]);
            }
        }
        __syncthreads();
    }

    // ----- write logits to smem (reference-order epilogue arithmetic) -----
    float* Ls = smem;  // [BM][BN+1]
    float4 b1v = *reinterpret_cast<const float4*>(&b1[col0 + cb]);
    float4 cov = *reinterpret_cast<const float4*>(&coff[col0 + cb]);
#pragma unroll
    for (int i = 0; i < TM; i++) {
        float2 v0 = unpack2(acc[i][0]);
        float2 v1 = unpack2(acc[i][1]);
        float* L = &Ls[(rb + i) * (BN + 1) + cb];
        L[0] = (v0.x + b1v.x) * 3.0f + cov.x;
        L[1] = (v0.y + b1v.y) * 3.0f + cov.y;
        L[2] = (v1.x + b1v.z) * 3.0f + cov.z;
        L[3] = (v1.y + b1v.w) * 3.0f + cov.w;
    }
    __syncthreads();

    // ----- per-(row, group) softmax + sampling: 256 tasks = 128 rows x 2 groups -----
    const int row  = tid >> 1;
    const int grp  = tid & 1;
    const int grow = row0 + row;
    const int gcol = col0 + grp * CG_NUM;
    const int ggrp = gcol >> 5;
    const float* L = &Ls[row * (BN + 1) + grp * CG_NUM];

    float m = -INFINITY;
#pragma unroll
    for (int j = 0; j < 32; j++) m = fmaxf(m, L[j]);
    float s = 0.0f;
#pragma unroll
    for (int j = 0; j < 32; j++) s += expf(L[j] - m);
    float logs = logf(s);

    const float4* G1 = reinterpret_cast<const float4*>(&g1[grow * C_DIM + gcol]);
    const float4* G2 = reinterpret_cast<const float4*>(&g2[grow * C_DIM + gcol]);
    int i1 = 0, i2 = 0;
    float bv1 = -INFINITY, bv2 = -INFINITY;
#pragma unroll
    for (int q = 0; q < 8; q++) {
        float4 a = G1[q];
        float4 b = G2[q];
        float lp;
        lp = (L[q * 4 + 0] - m) - logs;
        { float v = lp + a.x; if (v > bv1) { bv1 = v; i1 = q * 4 + 0; }
          float u = lp + b.x; if (u > bv2) { bv2 = u; i2 = q * 4 + 0; } }
        lp = (L[q * 4 + 1] - m) - logs;
        { float v = lp + a.y; if (v > bv1) { bv1 = v; i1 = q * 4 + 1; }
          float u = lp + b.y; if (u > bv2) { bv2 = u; i2 = q * 4 + 1; } }
        lp = (L[q * 4 + 2] - m) - logs;
        { float v = lp + a.z; if (v > bv1) { bv1 = v; i1 = q * 4 + 2; }
          float u = lp + b.z; if (u > bv2) { bv2 = u; i2 = q * 4 + 2; } }
        lp = (L[q * 4 + 3] - m) - logs;
        { float v = lp + a.w; if (v > bv1) { bv1 = v; i1 = q * 4 + 3; }
          float u = lp + b.w; if (u > bv2) { bv2 = u; i2 = q * 4 + 3; } }
    }

    // softmax write
    float invs = 1.0f / s;
    float* OS = &out_soft[grow * C_DIM + gcol];
#pragma unroll
    for (int q = 0; q < 8; q++) {
        float4 sv;
        sv.x = expf(L[q * 4 + 0] - m) * invs;
        sv.y = expf(L[q * 4 + 1] - m) * invs;
        sv.z = expf(L[q * 4 + 2] - m) * invs;
        sv.w = expf(L[q * 4 + 3] - m) * invs;
        reinterpret_cast<float4*>(OS)[q] = sv;
    }
    float soft_i1 = expf(L[i1] - m) * invs;
    float soft_i2 = expf(L[i2] - m) * invs;

    // straight-through values (forward): soft + (hard - soft)
    float uu = uint_[grow * G_NUM + ggrp];
    float ww = wint[grow * G_NUM + ggrp];
    float v1 = (uu < 1.0f) ? ww : 1.0f;
    float v2 = (uu < 1.0f) ? (1.0f - ww) : 0.0f;
    float c1, c2;
    if (i1 == i2) {
        c1 = soft_i1 + ((v1 + v2) - soft_i1);
        c2 = 0.0f;
    } else {
        c1 = soft_i1 + (v1 - soft_i1);
        c2 = soft_i2 + (v2 - soft_i2);
    }

    float* OSM = &out_sampled[grow * C_DIM + gcol];
#pragma unroll
    for (int q = 0; q < 8; q++) {
        float4 sv;
        int j0 = q * 4;
        sv.x = ((j0 + 0 == i1) ? c1 : 0.0f) + ((j0 + 0 == i2) ? c2 : 0.0f);
        sv.y = ((j0 + 1 == i1) ? c1 : 0.0f) + ((j0 + 1 == i2) ? c2 : 0.0f);
        sv.z = ((j0 + 2 == i1) ? c1 : 0.0f) + ((j0 + 2 == i2) ? c2 : 0.0f);
        sv.w = ((j0 + 3 == i1) ? c1 : 0.0f) + ((j0 + 3 == i2) ? c2 : 0.0f);
        reinterpret_cast<float4*>(OSM)[q] = sv;
    }

    int slot = grow * G_NUM + ggrp;
    g_idx[slot] = i1 | (i2 << 8);
    g_coef[2 * slot + 0] = c1;
    g_coef[2 * slot + 1] = c2;
}

// ---------- K2: sparse projection (gather W2T columns via SMEM stage) + LayerNorm ----------
__global__ __launch_bounds__(512)
void k_proj_ln(const float* __restrict__ b2, const float* __restrict__ gamma,
               const float* __restrict__ beta,
               float* __restrict__ out_pos, float* __restrict__ out_neg) {
    extern __shared__ float stage[];  // 32 * 512 floats = 64 KB
    const int tid = threadIdx.x;
    const int lane = tid & 31;
    const int wid  = tid >> 5;               // 16 warps, 4 rows each
    const int rowbase = blockIdx.x * 64;

    float4 h[4][4];
#pragma unroll
    for (int q = 0; q < 4; q++)
#pragma unroll
        for (int k = 0; k < 4; k++) h[q][k] = make_float4(0.f, 0.f, 0.f, 0.f);

    for (int g = 0; g < G_NUM; g++) {
        __syncthreads();  // previous stage fully consumed
        const float4* src = reinterpret_cast<const float4*>(&g_W2T[g * CG_NUM * E_DIM]);
        float4* dst = reinterpret_cast<float4*>(stage);
#pragma unroll
        for (int p = 0; p < 8; p++) dst[p * 512 + tid] = src[p * 512 + tid];
        __syncthreads();
#pragma unroll
        for (int q = 0; q < 4; q++) {
            int grow = rowbase + wid * 4 + q;
            int slot = grow * G_NUM + g;
            int packed = g_idx[slot];
            int i1 = packed & 255;
            int i2 = (packed >> 8) & 255;
            float c1 = g_coef[2 * slot + 0];
            float c2 = g_coef[2 * slot + 1];
            const float* s1 = &stage[i1 * E_DIM];
            const float* s2 = &stage[i2 * E_DIM];
#pragma unroll
            for (int k = 0; k < 4; k++) {
                float4 a = *reinterpret_cast<const float4*>(&s1[lane * 4 + 128 * k]);
                float4 b = *reinterpret_cast<const float4*>(&s2[lane * 4 + 128 * k]);
                h[q][k].x = fmaf(c1, a.x, fmaf(c2, b.x, h[q][k].x));
                h[q][k].y = fmaf(c1, a.y, fmaf(c2, b.y, h[q][k].y));
                h[q][k].z = fmaf(c1, a.z, fmaf(c2, b.z, h[q][k].z));
                h[q][k].w = fmaf(c1, a.w, fmaf(c2, b.w, h[q][k].w));
            }
        }
    }

    float4 b2r[4], gr[4], br[4];
#pragma unroll
    for (int k = 0; k < 4; k++) {
        b2r[k] = *reinterpret_cast<const float4*>(&b2[lane * 4 + 128 * k]);
        gr[k]  = *reinterpret_cast<const float4*>(&gamma[lane * 4 + 128 * k]);
        br[k]  = *reinterpret_cast<const float4*>(&beta[lane * 4 + 128 * k]);
    }

#pragma unroll
    for (int q = 0; q < 4; q++) {
        int grow = rowbase + wid * 4 + q;
        float sum = 0.0f;
#pragma unroll
        for (int k = 0; k < 4; k++) {
            h[q][k].x += b2r[k].x; h[q][k].y += b2r[k].y;
            h[q][k].z += b2r[k].z; h[q][k].w += b2r[k].w;
            sum += h[q][k].x + h[q][k].y + h[q][k].z + h[q][k].w;
        }
#pragma unroll
        for (int o = 16; o > 0; o >>= 1) sum += __shfl_xor_sync(0xffffffffu, sum, o);
        float mu = sum * (1.0f / 512.0f);
        float vs = 0.0f;
#pragma unroll
        for (int k = 0; k < 4; k++) {
            float dx;
            dx = h[q][k].x - mu; vs += dx * dx;
            dx = h[q][k].y - mu; vs += dx * dx;
            dx = h[q][k].z - mu; vs += dx * dx;
            dx = h[q][k].w - mu; vs += dx * dx;
        }
#pragma unroll
        for (int o = 16; o > 0; o >>= 1) vs += __shfl_xor_sync(0xffffffffu, vs, o);
        float var = vs * (1.0f / 512.0f);
        float sc = rsqrtf(var + 1e-5f);
#pragma unroll
        for (int k = 0; k < 4; k++) {
            float4 o4;
            o4.x = (h[q][k].x - mu) * sc * gr[k].x + br[k].x;
            o4.y = (h[q][k].y - mu) * sc * gr[k].y + br[k].y;
            o4.z = (h[q][k].z - mu) * sc * gr[k].z + br[k].z;
            o4.w = (h[q][k].w - mu) * sc * gr[k].w + br[k].w;
            int off = grow * E_DIM + lane * 4 + 128 * k;
            *reinterpret_cast<float4*>(&out_pos[off]) = o4;
            *reinterpret_cast<float4*>(&out_neg[off]) = o4;
        }
    }
}

extern "C" void kernel_launch(void* const* d_in, const int* in_sizes, int n_in,
                              void* d_out, int out_size) {
    const float* x     = (const float*)d_in[0];
    const float* W1    = (const float*)d_in[1];
    const float* b1    = (const float*)d_in[2];
    const float* coff  = (const float*)d_in[3];
    const float* W2    = (const float*)d_in[4];
    const float* b2    = (const float*)d_in[5];
    const float* gamma = (const float*)d_in[6];
    const float* beta  = (const float*)d_in[7];
    const float* g1    = (const float*)d_in[8];
    const float* g2    = (const float*)d_in[9];
    const float* wi    = (const float*)d_in[10];
    const float* ui    = (const float*)d_in[11];

    float* out = (float*)d_out;
    float* out_sampled = out;
    float* out_soft    = out + (size_t)SN * C_DIM;
    float* out_pos     = out + (size_t)2 * SN * C_DIM;
    float* out_neg     = out_pos + (size_t)SN * E_DIM;

    k_transpose<<<dim3(32, 16), dim3(32, 8)>>>(W2);
    k_gemm_sample<<<dim3(C_DIM / BN, SN / BM), 256>>>(x, W1, b1, coff, g1, g2, wi, ui,
                                                      out_sampled, out_soft);
    cudaFuncSetAttribute(k_proj_ln, cudaFuncAttributeMaxDynamicSharedMemorySize, 65536);
    k_proj_ln<<<SN / 64, 512, 65536>>>(b2, gamma, beta, out_pos, out_neg);
}

// round 6
// speedup vs baseline: 1.1119x; 1.1119x over previous
#include <cuda_runtime.h>
#include <math.h>
#include <stdint.h>

#define SN     16384
#define E_DIM  512
#define C_DIM  1024
#define G_NUM  32
#define CG_NUM 32

// ---------------- scratch (static device globals: no runtime allocation) ----------------
__device__ float g_W2T[C_DIM * E_DIM];   // W2 transposed to (C, E)
__device__ int   g_idx[SN * G_NUM];      // packed argmax indices
__device__ float g_coef[SN * G_NUM * 2]; // straight-through coefficients

// ---------------- packed fp32x2 helpers ----------------
static __device__ __forceinline__ unsigned long long pack2(float x, float y) {
    unsigned long long u;
    asm("mov.b64 %0, {%1, %2};" : "=l"(u) : "f"(x), "f"(y));
    return u;
}
static __device__ __forceinline__ float2 unpack2(unsigned long long u) {
    float2 v;
    asm("mov.b64 {%0, %1}, %2;" : "=f"(v.x), "=f"(v.y) : "l"(u));
    return v;
}
static __device__ __forceinline__ unsigned long long ffma2(unsigned long long a,
                                                           unsigned long long b,
                                                           unsigned long long c) {
    unsigned long long d;
    asm("fma.rn.f32x2 %0, %1, %2, %3;" : "=l"(d) : "l"(a), "l"(b), "l"(c));
    return d;
}

// ---------------- K0: transpose W2 (E, C) -> g_W2T (C, E) ----------------
__global__ void k_transpose(const float* __restrict__ W2) {
    __shared__ float tile[32][33];
    const int bx = blockIdx.x, by = blockIdx.y;
    const int tx = threadIdx.x, ty = threadIdx.y;
#pragma unroll
    for (int j = 0; j < 4; j++) {
        int e = by * 32 + ty + j * 8;
        int c = bx * 32 + tx;
        tile[ty + j * 8][tx] = W2[e * C_DIM + c];
    }
    __syncthreads();
#pragma unroll
    for (int j = 0; j < 4; j++) {
        int c = bx * 32 + ty + j * 8;
        int e = by * 32 + tx;
        g_W2T[c * E_DIM + e] = tile[tx][ty + j * 8];
    }
}

// ---------------- K1: fp32 FFMA2 GEMM (seq-k, bitwise == R2) + softmax/sampling ----------------
#define BM 128
#define BN 128
#define BK 16
#define NCH (E_DIM / BK)           // 32
#define LSTR 129                   // logits smem stride (floats): conflict-free task reads
#define SM_STAGE_FLOATS 8192       // As[2][16][128] + Bs[2][16][128]
#define SM_LOGITS_FLOATS (BM * LSTR)       // 16512
#define SM_BIAS_OFF SM_LOGITS_FLOATS       // b1s[128] then coffs[128]
#define K1_SMEM_BYTES ((SM_LOGITS_FLOATS + 256) * 4)   // 67072

__global__ __launch_bounds__(256, 2)
void k1_gemm(const float* __restrict__ x, const float* __restrict__ W1,
             const float* __restrict__ b1, const float* __restrict__ coff,
             const float* __restrict__ g1, const float* __restrict__ g2,
             const float* __restrict__ wint, const float* __restrict__ uin,
             float* __restrict__ out_sampled, float* __restrict__ out_soft) {
    extern __shared__ float S[];
    float* As = S;                       // [2][16][128]
    float* Bs = S + 4096;                // [2][16][128]
    float* Ls = S;                       // [128][129] (union with stage)
    float* b1s = S + SM_BIAS_OFF;        // [128]
    float* cfs = S + SM_BIAS_OFF + 128;  // [128]

    const int tid = threadIdx.x;
    const int tx = tid & 15;             // 0..15 (col groups)
    const int ty = tid >> 4;             // 0..15 (row groups)
    const int rb = ty * 8;
    const int cb1 = tx * 4;
    const int cb2 = 64 + tx * 4;
    const int row0 = blockIdx.y * BM;
    const int col0 = blockIdx.x * BN;

    if (tid < 128) { b1s[tid] = b1[col0 + tid]; cfs[tid] = coff[col0 + tid]; }

    unsigned long long acc[8][4];
#pragma unroll
    for (int i = 0; i < 8; i++)
#pragma unroll
        for (int p = 0; p < 4; p++) acc[i][p] = 0ull;

    float4 ra[2], rw[2];
    // prologue: load + stage chunk 0
#pragma unroll
    for (int i = 0; i < 2; i++) {
        int u = i * 256 + tid;
        int kq = u & 3, rr = u >> 2;
        ra[i] = *(const float4*)&x[(size_t)(row0 + rr) * E_DIM + kq * 4];
        rw[i] = *(const float4*)&W1[(size_t)(col0 + rr) * E_DIM + kq * 4];
    }
#pragma unroll
    for (int i = 0; i < 2; i++) {
        int u = i * 256 + tid;
        int kq = u & 3, rr = u >> 2;
        As[(kq * 4 + 0) * 128 + rr] = ra[i].x;
        As[(kq * 4 + 1) * 128 + rr] = ra[i].y;
        As[(kq * 4 + 2) * 128 + rr] = ra[i].z;
        As[(kq * 4 + 3) * 128 + rr] = ra[i].w;
        Bs[(kq * 4 + 0) * 128 + rr] = rw[i].x;
        Bs[(kq * 4 + 1) * 128 + rr] = rw[i].y;
        Bs[(kq * 4 + 2) * 128 + rr] = rw[i].z;
        Bs[(kq * 4 + 3) * 128 + rr] = rw[i].w;
    }
    __syncthreads();

    for (int c = 0; c < NCH; c++) {
        const int bo = (c & 1) * 2048;
        if (c + 1 < NCH) {
            const int kk = (c + 1) * BK;
#pragma unroll
            for (int i = 0; i < 2; i++) {
                int u = i * 256 + tid;
                int kq = u & 3, rr = u >> 2;
                ra[i] = *(const float4*)&x[(size_t)(row0 + rr) * E_DIM + kk + kq * 4];
                rw[i] = *(const float4*)&W1[(size_t)(col0 + rr) * E_DIM + kk + kq * 4];
            }
        }
#pragma unroll
        for (int k = 0; k < BK; k++) {
            const ulonglong2 bl = *(const ulonglong2*)(Bs + bo + k * 128 + cb1);
            const ulonglong2 bh = *(const ulonglong2*)(Bs + bo + k * 128 + cb2);
            const float4 al = *(const float4*)(As + bo + k * 128 + rb);
            const float4 ah = *(const float4*)(As + bo + k * 128 + rb + 4);
            const float av[8] = { al.x, al.y, al.z, al.w, ah.x, ah.y, ah.z, ah.w };
#pragma unroll
            for (int i = 0; i < 8; i++) {
                unsigned long long aa = pack2(av[i], av[i]);
                acc[i][0] = ffma2(aa, bl.x, acc[i][0]);
                acc[i][1] = ffma2(aa, bl.y, acc[i][1]);
                acc[i][2] = ffma2(aa, bh.x, acc[i][2]);
                acc[i][3] = ffma2(aa, bh.y, acc[i][3]);
            }
        }
        if (c + 1 < NCH) {
            __syncthreads();
            const int bn = ((c + 1) & 1) * 2048;
#pragma unroll
            for (int i = 0; i < 2; i++) {
                int u = i * 256 + tid;
                int kq = u & 3, rr = u >> 2;
                As[bn + (kq * 4 + 0) * 128 + rr] = ra[i].x;
                As[bn + (kq * 4 + 1) * 128 + rr] = ra[i].y;
                As[bn + (kq * 4 + 2) * 128 + rr] = ra[i].z;
                As[bn + (kq * 4 + 3) * 128 + rr] = ra[i].w;
                Bs[bn + (kq * 4 + 0) * 128 + rr] = rw[i].x;
                Bs[bn + (kq * 4 + 1) * 128 + rr] = rw[i].y;
                Bs[bn + (kq * 4 + 2) * 128 + rr] = rw[i].z;
                Bs[bn + (kq * 4 + 3) * 128 + rr] = rw[i].w;
            }
            __syncthreads();
        }
    }
    __syncthreads();   // stage fully consumed before logits overwrite

    // ----- logits to smem: (acc + b1) * 3 + coff  (reference order) -----
#pragma unroll
    for (int i = 0; i < 8; i++) {
        const int row = rb + i;
#pragma unroll
        for (int p = 0; p < 4; p++) {
            const int cc = (p < 2) ? (cb1 + p * 2) : (cb2 + (p - 2) * 2);
            float2 v = unpack2(acc[i][p]);
            Ls[row * LSTR + cc]     = (v.x + b1s[cc])     * 3.0f + cfs[cc];
            Ls[row * LSTR + cc + 1] = (v.y + b1s[cc + 1]) * 3.0f + cfs[cc + 1];
        }
    }

    // ----- zero-fill the sampled output tile (coalesced) -----
    {
        const float4 z = make_float4(0.f, 0.f, 0.f, 0.f);
#pragma unroll
        for (int v = 0; v < 16; v++) {
            int u = v * 256 + tid;
            int row = u >> 5, q = u & 31;
            *(float4*)&out_sampled[(size_t)(row0 + row) * C_DIM + col0 + q * 4] = z;
        }
    }
    __syncthreads();

    // ----- per-(row, group) softmax + Gumbel sampling: 512 tasks / 256 threads -----
#pragma unroll 1
    for (int p = 0; p < 2; p++) {
        const int task = p * 256 + tid;
        const int row = task & 127;             // warp = consecutive rows -> conflict-free LDS
        const int gg  = task >> 7;              // 0..3
        const int grow = row0 + row;
        const int gcol = col0 + gg * CG_NUM;
        const int ggrp = gcol >> 5;
        float* Lp = &Ls[row * LSTR + gg * CG_NUM];

        float L[32];
#pragma unroll
        for (int j = 0; j < 32; j++) L[j] = Lp[j];

        float m = -INFINITY;
#pragma unroll
        for (int j = 0; j < 32; j++) m = fmaxf(m, L[j]);
        float e[32];
        float s = 0.0f;
#pragma unroll
        for (int j = 0; j < 32; j++) { e[j] = expf(L[j] - m); s += e[j]; }
        float logs = logf(s);
        float invs = 1.0f / s;

        const float4* G1 = (const float4*)&g1[(size_t)grow * C_DIM + gcol];
        const float4* G2 = (const float4*)&g2[(size_t)grow * C_DIM + gcol];
        int i1 = 0, i2 = 0;
        float bv1 = -INFINITY, bv2 = -INFINITY;
#pragma unroll
        for (int q = 0; q < 8; q++) {
            float4 a = G1[q];
            float4 b = G2[q];
            float lp;
            lp = (L[q * 4 + 0] - m) - logs;
            { float v = lp + a.x; if (v > bv1) { bv1 = v; i1 = q * 4 + 0; }
              float u = lp + b.x; if (u > bv2) { bv2 = u; i2 = q * 4 + 0; } }
            lp = (L[q * 4 + 1] - m) - logs;
            { float v = lp + a.y; if (v > bv1) { bv1 = v; i1 = q * 4 + 1; }
              float u = lp + b.y; if (u > bv2) { bv2 = u; i2 = q * 4 + 1; } }
            lp = (L[q * 4 + 2] - m) - logs;
            { float v = lp + a.z; if (v > bv1) { bv1 = v; i1 = q * 4 + 2; }
              float u = lp + b.z; if (u > bv2) { bv2 = u; i2 = q * 4 + 2; } }
            lp = (L[q * 4 + 3] - m) - logs;
            { float v = lp + a.w; if (v > bv1) { bv1 = v; i1 = q * 4 + 3; }
              float u = lp + b.w; if (u > bv2) { bv2 = u; i2 = q * 4 + 3; } }
        }

        float soft_i1 = e[i1] * invs;
        float soft_i2 = e[i2] * invs;

        float uu = uin[grow * G_NUM + ggrp];
        float ww = wint[grow * G_NUM + ggrp];
        float v1 = (uu < 1.0f) ? ww : 1.0f;
        float v2 = (uu < 1.0f) ? (1.0f - ww) : 0.0f;
        float c1, c2;
        if (i1 == i2) { c1 = soft_i1 + ((v1 + v2) - soft_i1); c2 = 0.0f; }
        else          { c1 = soft_i1 + (v1 - soft_i1); c2 = soft_i2 + (v2 - soft_i2); }

        // sampled: sparse scatter over the zero-filled tile
        out_sampled[(size_t)grow * C_DIM + gcol + i1] = c1;
        if (i2 != i1) out_sampled[(size_t)grow * C_DIM + gcol + i2] = c2;

        // softmax values overwrite the logits slots (consumed above)
#pragma unroll
        for (int j = 0; j < 32; j++) Lp[j] = e[j] * invs;

        int slot = grow * G_NUM + ggrp;
        g_idx[slot] = i1 | (i2 << 8);
        g_coef[2 * slot + 0] = c1;
        g_coef[2 * slot + 1] = c2;
    }
    __syncthreads();

    // ----- cooperative coalesced copy of softmax out of smem -----
#pragma unroll
    for (int v = 0; v < 16; v++) {
        int u = v * 256 + tid;
        int row = u >> 5, q = u & 31;
        float4 sv;
        sv.x = Ls[row * LSTR + q * 4 + 0];
        sv.y = Ls[row * LSTR + q * 4 + 1];
        sv.z = Ls[row * LSTR + q * 4 + 2];
        sv.w = Ls[row * LSTR + q * 4 + 3];
        *(float4*)&out_soft[(size_t)(row0 + row) * C_DIM + col0 + q * 4] = sv;
    }
}

// ---------------- K2: sparse projection (SMEM-staged gather) + LayerNorm ----------------
__global__ __launch_bounds__(512)
void k_proj_ln(const float* __restrict__ b2, const float* __restrict__ gamma,
               const float* __restrict__ beta,
               float* __restrict__ out_pos, float* __restrict__ out_neg) {
    extern __shared__ float stage[];  // 32 * 512 floats = 64 KB
    const int tid = threadIdx.x;
    const int lane = tid & 31;
    const int wid  = tid >> 5;
    const int rowbase = blockIdx.x * 64;

    float4 h[4][4];
#pragma unroll
    for (int q = 0; q < 4; q++)
#pragma unroll
        for (int k = 0; k < 4; k++) h[q][k] = make_float4(0.f, 0.f, 0.f, 0.f);

    for (int g = 0; g < G_NUM; g++) {
        __syncthreads();
        const float4* src = reinterpret_cast<const float4*>(&g_W2T[g * CG_NUM * E_DIM]);
        float4* dst = reinterpret_cast<float4*>(stage);
#pragma unroll
        for (int p = 0; p < 8; p++) dst[p * 512 + tid] = src[p * 512 + tid];
        __syncthreads();
#pragma unroll
        for (int q = 0; q < 4; q++) {
            int grow = rowbase + wid * 4 + q;
            int slot = grow * G_NUM + g;
            int packed = g_idx[slot];
            int i1 = packed & 255;
            int i2 = (packed >> 8) & 255;
            float c1 = g_coef[2 * slot + 0];
            float c2 = g_coef[2 * slot + 1];
            const float* s1 = &stage[i1 * E_DIM];
            const float* s2 = &stage[i2 * E_DIM];
#pragma unroll
            for (int k = 0; k < 4; k++) {
                float4 a = *reinterpret_cast<const float4*>(&s1[lane * 4 + 128 * k]);
                float4 b = *reinterpret_cast<const float4*>(&s2[lane * 4 + 128 * k]);
                h[q][k].x = fmaf(c1, a.x, fmaf(c2, b.x, h[q][k].x));
                h[q][k].y = fmaf(c1, a.y, fmaf(c2, b.y, h[q][k].y));
                h[q][k].z = fmaf(c1, a.z, fmaf(c2, b.z, h[q][k].z));
                h[q][k].w = fmaf(c1, a.w, fmaf(c2, b.w, h[q][k].w));
            }
        }
    }

    float4 b2r[4], gr[4], br[4];
#pragma unroll
    for (int k = 0; k < 4; k++) {
        b2r[k] = *reinterpret_cast<const float4*>(&b2[lane * 4 + 128 * k]);
        gr[k]  = *reinterpret_cast<const float4*>(&gamma[lane * 4 + 128 * k]);
        br[k]  = *reinterpret_cast<const float4*>(&beta[lane * 4 + 128 * k]);
    }

#pragma unroll
    for (int q = 0; q < 4; q++) {
        int grow = rowbase + wid * 4 + q;
        float sum = 0.0f;
#pragma unroll
        for (int k = 0; k < 4; k++) {
            h[q][k].x += b2r[k].x; h[q][k].y += b2r[k].y;
            h[q][k].z += b2r[k].z; h[q][k].w += b2r[k].w;
            sum += h[q][k].x + h[q][k].y + h[q][k].z + h[q][k].w;
        }
#pragma unroll
        for (int o = 16; o > 0; o >>= 1) sum += __shfl_xor_sync(0xffffffffu, sum, o);
        float mu = sum * (1.0f / 512.0f);
        float vs = 0.0f;
#pragma unroll
        for (int k = 0; k < 4; k++) {
            float dx;
            dx = h[q][k].x - mu; vs += dx * dx;
            dx = h[q][k].y - mu; vs += dx * dx;
            dx = h[q][k].z - mu; vs += dx * dx;
            dx = h[q][k].w - mu; vs += dx * dx;
        }
#pragma unroll
        for (int o = 16; o > 0; o >>= 1) vs += __shfl_xor_sync(0xffffffffu, vs, o);
        float var = vs * (1.0f / 512.0f);
        float sc = rsqrtf(var + 1e-5f);
#pragma unroll
        for (int k = 0; k < 4; k++) {
            float4 o4;
            o4.x = (h[q][k].x - mu) * sc * gr[k].x + br[k].x;
            o4.y = (h[q][k].y - mu) * sc * gr[k].y + br[k].y;
            o4.z = (h[q][k].z - mu) * sc * gr[k].z + br[k].z;
            o4.w = (h[q][k].w - mu) * sc * gr[k].w + br[k].w;
            int off = grow * E_DIM + lane * 4 + 128 * k;
            *reinterpret_cast<float4*>(&out_pos[off]) = o4;
            *reinterpret_cast<float4*>(&out_neg[off]) = o4;
        }
    }
}

extern "C" void kernel_launch(void* const* d_in, const int* in_sizes, int n_in,
                              void* d_out, int out_size) {
    const float* x     = (const float*)d_in[0];
    const float* W1    = (const float*)d_in[1];
    const float* b1    = (const float*)d_in[2];
    const float* coff  = (const float*)d_in[3];
    const float* W2    = (const float*)d_in[4];
    const float* b2    = (const float*)d_in[5];
    const float* gamma = (const float*)d_in[6];
    const float* beta  = (const float*)d_in[7];
    const float* g1    = (const float*)d_in[8];
    const float* g2    = (const float*)d_in[9];
    const float* wi    = (const float*)d_in[10];
    const float* ui    = (const float*)d_in[11];

    float* out = (float*)d_out;
    float* out_sampled = out;
    float* out_soft    = out + (size_t)SN * C_DIM;
    float* out_pos     = out + (size_t)2 * SN * C_DIM;
    float* out_neg     = out_pos + (size_t)SN * E_DIM;

    k_transpose<<<dim3(32, 16), dim3(32, 8)>>>(W2);

    cudaFuncSetAttribute(k1_gemm, cudaFuncAttributeMaxDynamicSharedMemorySize, K1_SMEM_BYTES);
    k1_gemm<<<dim3(C_DIM / BN, SN / BM), 256, K1_SMEM_BYTES>>>(
        x, W1, b1, coff, g1, g2, wi, ui, out_sampled, out_soft);

    cudaFuncSetAttribute(k_proj_ln, cudaFuncAttributeMaxDynamicSharedMemorySize, 65536);
    k_proj_ln<<<SN / 64, 512, 65536>>>(b2, gamma, beta, out_pos, out_neg);
}